// round 12
// baseline (speedup 1.0000x reference)
#include <cuda_runtime.h>
#include <cuda_bf16.h>

// Problem constants
#define B_ 4
#define T_ 1024
#define C_ 1024
#define H_ 16
#define L_ 256
#define D_ 64
#define M_ (B_*T_)   // 4096 rows

// ---------------------------------------------------------------------------
// Scratch (device globals: no allocation allowed in kernel_launch)
// ---------------------------------------------------------------------------
__device__ float    g_kv_down[M_ * L_];          //  4 MB
__device__ float    g_q_down [M_ * L_];          //  4 MB
__device__ unsigned g_khi[M_ * C_ / 2];          //  8 MB  bf16 pairs (b,t,h,d)
__device__ unsigned g_klo[M_ * C_ / 2];          //  8 MB
__device__ unsigned g_qhi[M_ * C_ / 2];          //  8 MB  (pre-scaled 0.125)
__device__ unsigned g_qlo[M_ * C_ / 2];          //  8 MB
__device__ unsigned g_vhi_t[M_ * C_ / 2];        //  8 MB  (b,t,h,d)
__device__ unsigned g_vlo_t[M_ * C_ / 2];        //  8 MB
__device__ unsigned g_vhi_d[M_ * C_ / 2];        //  8 MB  (b,h,d,t) pairs along t
__device__ unsigned g_vlo_d[M_ * C_ / 2];        //  8 MB
__device__ float    g_ctx    [M_ * C_];          // 16 MB
__device__ float    g_interT [67108864];         // 256 MB: (B,H,Tq,Tk)

// ---------------------------------------------------------------------------
// bf16 split-precision helpers: a = hi + lo captures ~16 mantissa bits.
// ---------------------------------------------------------------------------
__device__ __forceinline__ unsigned bf16pair(float x, float y) {
    __nv_bfloat162 t = __floats2bfloat162_rn(x, y);
    return reinterpret_cast<unsigned&>(t);
}
__device__ __forceinline__ float bf16hi(float x) {
    return __bfloat162float(__float2bfloat16(x));
}
__device__ __forceinline__ void split2(unsigned& hi, unsigned& lo,
                                       float x, float y) {
    float hx = bf16hi(x), hy = bf16hi(y);
    hi = bf16pair(x, y);
    lo = bf16pair(x - hx, y - hy);
}

__device__ __forceinline__ void mma16816(float* c, const unsigned* a,
                                         const unsigned* b) {
    asm volatile(
        "mma.sync.aligned.m16n8k16.row.col.f32.bf16.bf16.f32 "
        "{%0,%1,%2,%3}, {%4,%5,%6,%7}, {%8,%9}, {%0,%1,%2,%3};"
        : "+f"(c[0]), "+f"(c[1]), "+f"(c[2]), "+f"(c[3])
        : "r"(a[0]), "r"(a[1]), "r"(a[2]), "r"(a[3]),
          "r"(b[0]), "r"(b[1]));
}

// ---------------------------------------------------------------------------
// Tensor-core GEMM, bf16 2-term split (3 mma per product: hh + hl + lh).
// C[M,N] = A[M,K] @ B[K,N]. Epilogue: if Chi != nullptr, writes scaled bf16
// hi/lo pair words (for downstream zero-conversion consumers); else fp32+bias.
// Block tile 128x128, BK=32, 256 threads, warp tile 64x32.
// ---------------------------------------------------------------------------
__global__ __launch_bounds__(256, 2)
void hgemm_bf16x3(const float* __restrict__ A, const float* __restrict__ Bm,
                  float* __restrict__ Cm, unsigned* __restrict__ Chi,
                  unsigned* __restrict__ Clo, float scale,
                  int Mdim, int Ndim, int Kdim,
                  const float* __restrict__ bias)
{
    __shared__ unsigned Ahi[128 * 20];
    __shared__ unsigned Alo[128 * 20];
    __shared__ unsigned Bhi[16 * 136];
    __shared__ unsigned Blo[16 * 136];

    const int tid  = threadIdx.x;
    const int lane = tid & 31;
    const int wid  = tid >> 5;
    const int g    = lane >> 2;
    const int tg   = lane & 3;
    const int wm   = (wid & 1) * 64;
    const int wn   = (wid >> 1) * 32;
    const int m0   = blockIdx.y * 128;
    const int n0   = blockIdx.x * 128;

    float acc[4][4][4];
#pragma unroll
    for (int i = 0; i < 4; i++)
#pragma unroll
        for (int j = 0; j < 4; j++)
#pragma unroll
            for (int t = 0; t < 4; t++) acc[i][j][t] = 0.f;

    for (int k0 = 0; k0 < Kdim; k0 += 32) {
#pragma unroll
        for (int i = 0; i < 4; i++) {
            int idx = tid + i * 256;
            int row = idx >> 3;
            int f4  = idx & 7;
            float4 a = *(const float4*)&A[(size_t)(m0 + row) * Kdim + k0 + f4 * 4];
            int w = row * 20 + f4 * 2;
            Ahi[w]     = bf16pair(a.x, a.y);
            Ahi[w + 1] = bf16pair(a.z, a.w);
            Alo[w]     = bf16pair(a.x - bf16hi(a.x), a.y - bf16hi(a.y));
            Alo[w + 1] = bf16pair(a.z - bf16hi(a.z), a.w - bf16hi(a.w));
        }
        {
            __nv_bfloat16* ph = reinterpret_cast<__nv_bfloat16*>(Bhi);
            __nv_bfloat16* pl = reinterpret_cast<__nv_bfloat16*>(Blo);
#pragma unroll
            for (int i = 0; i < 4; i++) {
                int idx = tid + i * 256;
                int kr  = idx >> 5;
                int n4  = (idx & 31) * 4;
                float4 b = *(const float4*)&Bm[(size_t)(k0 + kr) * Ndim + n0 + n4];
                int hb = ((kr >> 1) * 136) * 2 + (kr & 1);
                float vs[4] = {b.x, b.y, b.z, b.w};
#pragma unroll
                for (int j = 0; j < 4; j++) {
                    float v = vs[j];
                    __nv_bfloat16 h = __float2bfloat16(v);
                    ph[hb + (n4 + j) * 2] = h;
                    pl[hb + (n4 + j) * 2] = __float2bfloat16(v - __bfloat162float(h));
                }
            }
        }
        __syncthreads();

#pragma unroll
        for (int s = 0; s < 2; s++) {
            const int pb = s * 8 + tg;
            unsigned bh[4][2], bl[4][2];
#pragma unroll
            for (int nt = 0; nt < 4; nt++) {
                int c = wn + nt * 8 + g;
                bh[nt][0] = Bhi[pb * 136 + c];
                bh[nt][1] = Bhi[(pb + 4) * 136 + c];
                bl[nt][0] = Blo[pb * 136 + c];
                bl[nt][1] = Blo[(pb + 4) * 136 + c];
            }
#pragma unroll
            for (int mt = 0; mt < 4; mt++) {
                int r = wm + mt * 16 + g;
                unsigned ah[4], al[4];
                ah[0] = Ahi[r * 20 + pb];
                ah[1] = Ahi[(r + 8) * 20 + pb];
                ah[2] = Ahi[r * 20 + pb + 4];
                ah[3] = Ahi[(r + 8) * 20 + pb + 4];
                al[0] = Alo[r * 20 + pb];
                al[1] = Alo[(r + 8) * 20 + pb];
                al[2] = Alo[r * 20 + pb + 4];
                al[3] = Alo[(r + 8) * 20 + pb + 4];
#pragma unroll
                for (int nt = 0; nt < 4; nt++) {
                    mma16816(acc[mt][nt], ah, bh[nt]);
                    mma16816(acc[mt][nt], ah, bl[nt]);
                    mma16816(acc[mt][nt], al, bh[nt]);
                }
            }
        }
        __syncthreads();
    }

    if (Chi) {
        const int nw = Ndim >> 1;
#pragma unroll
        for (int mt = 0; mt < 4; mt++) {
            int r = m0 + wm + mt * 16 + g;
#pragma unroll
            for (int nt = 0; nt < 4; nt++) {
                int wd = (n0 + wn + nt * 8 + tg * 2) >> 1;
                unsigned h0, l0, h1, l1;
                split2(h0, l0, acc[mt][nt][0] * scale, acc[mt][nt][1] * scale);
                split2(h1, l1, acc[mt][nt][2] * scale, acc[mt][nt][3] * scale);
                Chi[(size_t)r * nw + wd]       = h0;
                Clo[(size_t)r * nw + wd]       = l0;
                Chi[(size_t)(r + 8) * nw + wd] = h1;
                Clo[(size_t)(r + 8) * nw + wd] = l1;
            }
        }
    } else {
#pragma unroll
        for (int mt = 0; mt < 4; mt++) {
            int r = m0 + wm + mt * 16 + g;
#pragma unroll
            for (int nt = 0; nt < 4; nt++) {
                int c = n0 + wn + nt * 8 + tg * 2;
                float b0 = 0.f, b1 = 0.f;
                if (bias) { b0 = bias[c]; b1 = bias[c + 1]; }
                float2 v0 = make_float2(acc[mt][nt][0] + b0, acc[mt][nt][1] + b1);
                float2 v1 = make_float2(acc[mt][nt][2] + b0, acc[mt][nt][3] + b1);
                *(float2*)&Cm[(size_t)r * Ndim + c]       = v0;
                *(float2*)&Cm[(size_t)(r + 8) * Ndim + c] = v1;
            }
        }
    }
}

// ---------------------------------------------------------------------------
// V re-layout: (b,t,h,d) bf16 pairs-along-d  ->  (b,h,d,t) pairs-along-t.
// Grid (T/64, H, B), 128 threads. Tile = 64 t x 64 d, hi then lo pass.
// smem shorts stride 66: write-phase read banks (2kp + d/2)%32 -> 2-way max.
// Output writes: warp = 16 d-rows, lanes = 32 consecutive t-pair words =
// 128B coalesced.
// ---------------------------------------------------------------------------
__global__ __launch_bounds__(128)
void vtrans(const unsigned* __restrict__ srcH, const unsigned* __restrict__ srcL,
            unsigned* __restrict__ dstH, unsigned* __restrict__ dstL)
{
    __shared__ unsigned short s[64 * 66];
    const int tid  = threadIdx.x;
    const int lane = tid & 31;
    const int w    = tid >> 5;
    const int t0   = blockIdx.x * 64;
    const int h    = blockIdx.y;
    const int b    = blockIdx.z;

#pragma unroll
    for (int pass = 0; pass < 2; pass++) {
        const unsigned* sp = (pass ? srcL : srcH)
            + (size_t)(b * T_ + t0) * (C_ / 2) + h * (D_ / 2);
        unsigned* dp = (pass ? dstL : dstH)
            + ((size_t)(b * H_ + h) * D_) * (T_ / 2) + t0 / 2;

        if (pass) __syncthreads();
#pragma unroll
        for (int i = 0; i < 4; i++) {
            int idx = tid + i * 128;          // 0..511
            int tt  = idx >> 3;               // 0..63
            int w4  = (idx & 7) * 4;          // word offset 0..28
            uint4 v = *(const uint4*)&sp[(size_t)tt * (C_ / 2) + w4];
            unsigned* sm = (unsigned*)&s[tt * 66 + w4 * 2];
            sm[0] = v.x; sm[1] = v.y; sm[2] = v.z; sm[3] = v.w;
        }
        __syncthreads();

#pragma unroll
        for (int r = 0; r < 16; r++) {
            int d = w * 16 + r;
            unsigned lo = s[(2 * lane) * 66 + d];
            unsigned hi = s[(2 * lane + 1) * 66 + d];
            dp[(size_t)d * (T_ / 2) + lane] = lo | (hi << 16);
        }
    }
}

// ---------------------------------------------------------------------------
// interaction_matrix transpose v2: (B, Tk, Tq, H) -> (B, H, Tq, Tk).
// Unchanged from round 10 (validated).
// ---------------------------------------------------------------------------
__global__ __launch_bounds__(256)
void transpose_inter2(const float* __restrict__ src, float* __restrict__ dst)
{
    __shared__ float s[32 * 129];
    const int t    = threadIdx.x;
    const int lane = t & 31;
    const int w    = t >> 5;
    const int k0   = blockIdx.x * 32;
    const int q0   = blockIdx.y * 8;
    const int b    = blockIdx.z;

    const int k  = t >> 3;
    const int f4b = t & 7;
    const float* sp = src + (size_t)(b * T_ + k0 + k) * (T_ * H_) + q0 * H_;
#pragma unroll
    for (int p = 0; p < 4; p++) {
        int f4 = f4b + p * 8;
        float4 v = *(const float4*)&sp[f4 * 4];
        s[k * 129 + f4 * 4 + 0] = v.x;
        s[k * 129 + f4 * 4 + 1] = v.y;
        s[k * 129 + f4 * 4 + 2] = v.z;
        s[k * 129 + f4 * 4 + 3] = v.w;
    }
    __syncthreads();

#pragma unroll
    for (int r = 0; r < 16; r++) {
        int qh = w * 16 + r;
        int q  = qh >> 4;
        int h  = qh & 15;
        float v = s[lane * 129 + qh];
        dst[((size_t)(b * H_ + h) * T_ + q0 + q) * T_ + k0 + lane] = v;
    }
}

// ---------------------------------------------------------------------------
// Tensor-core flash attention v2: zero in-loop conversion. Q/K/V arrive as
// pre-split bf16 hi/lo words. Mainloop tile load = pure uint4 copies:
//   K (b,t,h,d) pairs-along-d -> smem [key][dpair] stride 36
//   V (b,h,d,t) pairs-along-t -> smem [d][keypair] stride 36
// Fragment bank maps: (4g+tg) fully distinct, conflict-free. Grid (T/64,H,B),
// 128 threads = 4 warps, each warp owns 16 q-rows, intra-warp reductions only.
// ---------------------------------------------------------------------------
__global__ __launch_bounds__(128)
void attn_mma2(const unsigned* __restrict__ Qhi, const unsigned* __restrict__ Qlo,
               const unsigned* __restrict__ Kh_g, const unsigned* __restrict__ Kl_g,
               const unsigned* __restrict__ Vh_g, const unsigned* __restrict__ Vl_g,
               const int* __restrict__ pad, const float* __restrict__ interT,
               float* __restrict__ ctx)
{
    __shared__ unsigned Khs[64 * 36], Kls[64 * 36];
    __shared__ unsigned Vhs[64 * 36], Vls[64 * 36];

    const float NEG = __int_as_float(0xff800000);   // -inf

    const int tid  = threadIdx.x;
    const int lane = tid & 31;
    const int w    = tid >> 5;
    const int g    = lane >> 2;
    const int tg   = lane & 3;
    const int q0   = blockIdx.x * 64;
    const int h    = blockIdx.y;
    const int b    = blockIdx.z;

    const int row0 = q0 + w * 16 + g;
    const int row1 = row0 + 8;

    // ---- Q fragments: direct word loads (already scaled by 0.125) ----
    const unsigned* qh0 = Qhi + (size_t)(b * T_ + row0) * (C_ / 2) + h * (D_ / 2) + tg;
    const unsigned* qh1 = qh0 + 8 * (C_ / 2);
    const unsigned* ql0 = Qlo + (size_t)(b * T_ + row0) * (C_ / 2) + h * (D_ / 2) + tg;
    const unsigned* ql1 = ql0 + 8 * (C_ / 2);
    unsigned ah[4][4], al[4][4];
#pragma unroll
    for (int s = 0; s < 4; s++) {
        ah[s][0] = qh0[8 * s];     ah[s][1] = qh1[8 * s];
        ah[s][2] = qh0[8 * s + 4]; ah[s][3] = qh1[8 * s + 4];
        al[s][0] = ql0[8 * s];     al[s][1] = ql1[8 * s];
        al[s][2] = ql0[8 * s + 4]; al[s][3] = ql1[8 * s + 4];
    }

    const int pd0 = pad[b * T_ + row0];
    const int pd1 = pad[b * T_ + row1];
    const float* ip0 = interT + ((size_t)(b * H_ + h) * T_ + row0) * T_ + 2 * tg;
    const float* ip1 = interT + ((size_t)(b * H_ + h) * T_ + row1) * T_ + 2 * tg;

    float m0 = NEG, m1 = NEG, l0 = 0.f, l1 = 0.f;
    float o[8][4];
#pragma unroll
    for (int j = 0; j < 8; j++)
#pragma unroll
        for (int i = 0; i < 4; i++) o[j][i] = 0.f;

    const unsigned* kh_b = Kh_g + (size_t)(b * T_) * (C_ / 2) + h * (D_ / 2);
    const unsigned* kl_b = Kl_g + (size_t)(b * T_) * (C_ / 2) + h * (D_ / 2);
    const unsigned* vh_b = Vh_g + ((size_t)(b * H_ + h) * D_) * (T_ / 2);
    const unsigned* vl_b = Vl_g + ((size_t)(b * H_ + h) * D_) * (T_ / 2);

    for (int k0 = 0; k0 < q0 + 64; k0 += 64) {
        __syncthreads();   // smem consumed by previous iteration's mma
        // ---- pure uint4 tile copies: K rows (t), V rows (d) ----
#pragma unroll
        for (int i = 0; i < 4; i++) {
            int idx = tid + i * 128;          // 0..511
            int rr  = idx >> 3;               // 0..63
            int w4  = (idx & 7) * 4;          // 0..28
            *(uint4*)&Khs[rr * 36 + w4] =
                *(const uint4*)&kh_b[(size_t)(k0 + rr) * (C_ / 2) + w4];
            *(uint4*)&Kls[rr * 36 + w4] =
                *(const uint4*)&kl_b[(size_t)(k0 + rr) * (C_ / 2) + w4];
            *(uint4*)&Vhs[rr * 36 + w4] =
                *(const uint4*)&vh_b[(size_t)rr * (T_ / 2) + k0 / 2 + w4];
            *(uint4*)&Vls[rr * 36 + w4] =
                *(const uint4*)&vl_b[(size_t)rr * (T_ / 2) + k0 / 2 + w4];
        }
        __syncthreads();

        // ---- bias loads (independent of mma; compiler overlaps) ----
        float2 bias0[8], bias1[8];
#pragma unroll
        for (int j = 0; j < 8; j++) {
            bias0[j] = *(const float2*)&ip0[k0 + 8 * j];
            bias1[j] = *(const float2*)&ip1[k0 + 8 * j];
        }

        // ---- S = (0.125*Q) K^T via split mma ----
        float sc[8][4];
#pragma unroll
        for (int j = 0; j < 8; j++)
#pragma unroll
            for (int i = 0; i < 4; i++) sc[j][i] = 0.f;
#pragma unroll
        for (int j = 0; j < 8; j++) {
            const int c = (8 * j + g) * 36;
#pragma unroll
            for (int st = 0; st < 4; st++) {
                unsigned bh[2] = {Khs[c + st * 8 + tg], Khs[c + st * 8 + tg + 4]};
                unsigned bl[2] = {Kls[c + st * 8 + tg], Kls[c + st * 8 + tg + 4]};
                mma16816(sc[j], ah[st], bh);
                mma16816(sc[j], ah[st], bl);
                mma16816(sc[j], al[st], bh);
            }
        }

        // ---- masks + bias + online softmax ----
        float mt0 = NEG, mt1 = NEG;
#pragma unroll
        for (int j = 0; j < 8; j++) {
            int kc = k0 + 8 * j + 2 * tg;
            float v0 = sc[j][0], v1 = sc[j][1], v2 = sc[j][2], v3 = sc[j][3];
            if (pd0 == 0) { v0 = -1e9f; v1 = -1e9f; }
            if (pd1 == 0) { v2 = -1e9f; v3 = -1e9f; }
            if (kc     > row0) v0 = NEG;
            if (kc + 1 > row0) v1 = NEG;
            if (kc     > row1) v2 = NEG;
            if (kc + 1 > row1) v3 = NEG;
            v0 += bias0[j].x; v1 += bias0[j].y;
            v2 += bias1[j].x; v3 += bias1[j].y;
            sc[j][0] = v0; sc[j][1] = v1; sc[j][2] = v2; sc[j][3] = v3;
            mt0 = fmaxf(mt0, fmaxf(v0, v1));
            mt1 = fmaxf(mt1, fmaxf(v2, v3));
        }
        mt0 = fmaxf(mt0, __shfl_xor_sync(0xffffffffu, mt0, 1));
        mt0 = fmaxf(mt0, __shfl_xor_sync(0xffffffffu, mt0, 2));
        mt1 = fmaxf(mt1, __shfl_xor_sync(0xffffffffu, mt1, 1));
        mt1 = fmaxf(mt1, __shfl_xor_sync(0xffffffffu, mt1, 2));

        float mn0 = fmaxf(m0, mt0), mn1 = fmaxf(m1, mt1);
        float f0 = __expf(m0 - mn0);
        float f1 = __expf(m1 - mn1);

        float lt0 = 0.f, lt1 = 0.f;
#pragma unroll
        for (int j = 0; j < 8; j++) {
            float p0 = __expf(sc[j][0] - mn0);
            float p1 = __expf(sc[j][1] - mn0);
            float p2 = __expf(sc[j][2] - mn1);
            float p3 = __expf(sc[j][3] - mn1);
            sc[j][0] = p0; sc[j][1] = p1; sc[j][2] = p2; sc[j][3] = p3;
            lt0 += p0 + p1; lt1 += p2 + p3;
        }
        lt0 += __shfl_xor_sync(0xffffffffu, lt0, 1);
        lt0 += __shfl_xor_sync(0xffffffffu, lt0, 2);
        lt1 += __shfl_xor_sync(0xffffffffu, lt1, 1);
        lt1 += __shfl_xor_sync(0xffffffffu, lt1, 2);
        l0 = l0 * f0 + lt0; m0 = mn0;
        l1 = l1 * f1 + lt1; m1 = mn1;

#pragma unroll
        for (int j = 0; j < 8; j++) {
            o[j][0] *= f0; o[j][1] *= f0;
            o[j][2] *= f1; o[j][3] *= f1;
        }

        // ---- P fragments: S accum layout == A-frag layout ----
        unsigned ph[4][4], pl[4][4];
#pragma unroll
        for (int s = 0; s < 4; s++) {
            split2(ph[s][0], pl[s][0], sc[2 * s][0],     sc[2 * s][1]);
            split2(ph[s][1], pl[s][1], sc[2 * s][2],     sc[2 * s][3]);
            split2(ph[s][2], pl[s][2], sc[2 * s + 1][0], sc[2 * s + 1][1]);
            split2(ph[s][3], pl[s][3], sc[2 * s + 1][2], sc[2 * s + 1][3]);
        }

        // ---- O += P V via split mma ----
#pragma unroll
        for (int j = 0; j < 8; j++) {
            const int c = (8 * j + g) * 36;
#pragma unroll
            for (int s = 0; s < 4; s++) {
                unsigned bh[2] = {Vhs[c + s * 8 + tg], Vhs[c + s * 8 + tg + 4]};
                unsigned bl[2] = {Vls[c + s * 8 + tg], Vls[c + s * 8 + tg + 4]};
                mma16816(o[j], ph[s], bh);
                mma16816(o[j], ph[s], bl);
                mma16816(o[j], pl[s], bh);
            }
        }
    }

    // ---- epilogue: normalize, write ctx (B,T,C) ----
    const float inv0 = 1.f / l0, inv1 = 1.f / l1;
    float* op0 = ctx + (size_t)(b * T_ + row0) * C_ + h * D_ + 2 * tg;
    float* op1 = ctx + (size_t)(b * T_ + row1) * C_ + h * D_ + 2 * tg;
#pragma unroll
    for (int j = 0; j < 8; j++) {
        *(float2*)&op0[8 * j] = make_float2(o[j][0] * inv0, o[j][1] * inv0);
        *(float2*)&op1[8 * j] = make_float2(o[j][2] * inv1, o[j][3] * inv1);
    }
}

// ---------------------------------------------------------------------------
// Launch sequence (default stream, graph-capturable):
//   down GEMMs -> up GEMMs with split-bf16 epilogues -> V relayout ->
//   interaction transpose -> zero-conversion mma attention -> output GEMM.
// ---------------------------------------------------------------------------
extern "C" void kernel_launch(void* const* d_in, const int* in_sizes, int n_in,
                              void* d_out, int out_size)
{
    const float* x       = (const float*)d_in[0];
    const int*   padding = (const int*)  d_in[1];
    const float* inter   = (const float*)d_in[2];
    const float* W_ckv   = (const float*)d_in[3];
    const float* W_cq    = (const float*)d_in[4];
    const float* W_kc    = (const float*)d_in[5];
    const float* W_qc    = (const float*)d_in[6];
    const float* W_vc    = (const float*)d_in[7];
    const float* W_proj  = (const float*)d_in[8];
    const float* b_proj  = (const float*)d_in[9];
    float* out = (float*)d_out;

    float *kv_down, *q_down, *ctx, *interT;
    unsigned *khi, *klo, *qhi, *qlo, *vhi_t, *vlo_t, *vhi_d, *vlo_d;
    cudaGetSymbolAddress((void**)&kv_down, g_kv_down);
    cudaGetSymbolAddress((void**)&q_down,  g_q_down);
    cudaGetSymbolAddress((void**)&khi,     g_khi);
    cudaGetSymbolAddress((void**)&klo,     g_klo);
    cudaGetSymbolAddress((void**)&qhi,     g_qhi);
    cudaGetSymbolAddress((void**)&qlo,     g_qlo);
    cudaGetSymbolAddress((void**)&vhi_t,   g_vhi_t);
    cudaGetSymbolAddress((void**)&vlo_t,   g_vlo_t);
    cudaGetSymbolAddress((void**)&vhi_d,   g_vhi_d);
    cudaGetSymbolAddress((void**)&vlo_d,   g_vlo_d);
    cudaGetSymbolAddress((void**)&ctx,     g_ctx);
    cudaGetSymbolAddress((void**)&interT,  g_interT);

    dim3 blk(256);

    // down projections: (4096x1024)@(1024x256), fp32 out
    hgemm_bf16x3<<<dim3(L_ / 128, M_ / 128), blk>>>(
        x, W_ckv, kv_down, nullptr, nullptr, 1.f, M_, L_, C_, nullptr);
    hgemm_bf16x3<<<dim3(L_ / 128, M_ / 128), blk>>>(
        x, W_cq, q_down, nullptr, nullptr, 1.f, M_, L_, C_, nullptr);

    // up projections: (4096x256)@(256x1024), split-bf16 out (Q pre-scaled)
    hgemm_bf16x3<<<dim3(C_ / 128, M_ / 128), blk>>>(
        kv_down, W_kc, nullptr, khi, klo, 1.f, M_, C_, L_, nullptr);
    hgemm_bf16x3<<<dim3(C_ / 128, M_ / 128), blk>>>(
        q_down, W_qc, nullptr, qhi, qlo, 0.125f, M_, C_, L_, nullptr);
    hgemm_bf16x3<<<dim3(C_ / 128, M_ / 128), blk>>>(
        kv_down, W_vc, nullptr, vhi_t, vlo_t, 1.f, M_, C_, L_, nullptr);

    // V relayout: (b,t,h,d) -> (b,h,d,t) pairs along t
    vtrans<<<dim3(T_ / 64, H_, B_), dim3(128)>>>(vhi_t, vlo_t, vhi_d, vlo_d);

    // interaction matrix (B,Tk,Tq,H) -> (B,H,Tq,Tk)
    transpose_inter2<<<dim3(T_ / 32, T_ / 8, B_), blk>>>(inter, interT);

    // attention -> ctx (B,T,C)
    attn_mma2<<<dim3(T_ / 64, H_, B_), dim3(128)>>>(
        qhi, qlo, khi, klo, vhi_d, vlo_d, padding, interT, ctx);

    // output projection: (4096x1024)@(1024x1024) + bias, fp32 out
    hgemm_bf16x3<<<dim3(C_ / 128, M_ / 128), blk>>>(
        ctx, W_proj, out, nullptr, nullptr, 1.f, M_, C_, C_, b_proj);
}

// round 14
// speedup vs baseline: 1.1888x; 1.1888x over previous
#include <cuda_runtime.h>
#include <cuda_bf16.h>

// Problem constants
#define B_ 4
#define T_ 1024
#define C_ 1024
#define H_ 16
#define L_ 256
#define D_ 64
#define M_ (B_*T_)   // 4096 rows

// ---------------------------------------------------------------------------
// Scratch (device globals: no allocation allowed in kernel_launch)
// ---------------------------------------------------------------------------
__device__ float g_kv_down[M_ * L_];            //  4 MB
__device__ float g_q_down [M_ * L_];            //  4 MB
__device__ float g_k      [M_ * C_];            // 16 MB  (B,T,C) row-major
__device__ float g_q      [M_ * C_];            // 16 MB
__device__ float g_v      [M_ * C_];            // 16 MB
__device__ float g_ctx    [M_ * C_];            // 16 MB
__device__ float g_interT [67108864];           // 256 MB: (B,H,Tq,Tk)

// ---------------------------------------------------------------------------
// bf16 split-precision helpers: a = hi + lo captures ~16 mantissa bits.
// ---------------------------------------------------------------------------
__device__ __forceinline__ unsigned bf16pair(float x, float y) {
    __nv_bfloat162 t = __floats2bfloat162_rn(x, y);
    return reinterpret_cast<unsigned&>(t);
}
__device__ __forceinline__ float bf16hi(float x) {
    return __bfloat162float(__float2bfloat16(x));
}
__device__ __forceinline__ void split2(unsigned& hi, unsigned& lo,
                                       float x, float y) {
    float hx = bf16hi(x), hy = bf16hi(y);
    hi = bf16pair(x, y);
    lo = bf16pair(x - hx, y - hy);
}

__device__ __forceinline__ void mma16816(float* c, const unsigned* a,
                                         const unsigned* b) {
    asm volatile(
        "mma.sync.aligned.m16n8k16.row.col.f32.bf16.bf16.f32 "
        "{%0,%1,%2,%3}, {%4,%5,%6,%7}, {%8,%9}, {%0,%1,%2,%3};"
        : "+f"(c[0]), "+f"(c[1]), "+f"(c[2]), "+f"(c[3])
        : "r"(a[0]), "r"(a[1]), "r"(a[2]), "r"(a[3]),
          "r"(b[0]), "r"(b[1]));
}

// ---------------------------------------------------------------------------
// Tensor-core GEMM, bf16 2-term split (3 mma per product: hh + hl + lh).
// C[M,N] = A[M,K] @ B[K,N] (+bias). Block tile 128x128, BK=32, 256 threads,
// warp tile 64x32. EXACT round-10 version (validated: 32.3us up-proj).
// ---------------------------------------------------------------------------
__global__ __launch_bounds__(256, 2)
void hgemm_bf16x3(const float* __restrict__ A, const float* __restrict__ Bm,
                  float* __restrict__ Cm, int Mdim, int Ndim, int Kdim,
                  const float* __restrict__ bias)
{
    __shared__ unsigned Ahi[128 * 20];
    __shared__ unsigned Alo[128 * 20];
    __shared__ unsigned Bhi[16 * 136];
    __shared__ unsigned Blo[16 * 136];

    const int tid  = threadIdx.x;
    const int lane = tid & 31;
    const int wid  = tid >> 5;
    const int g    = lane >> 2;
    const int tg   = lane & 3;
    const int wm   = (wid & 1) * 64;
    const int wn   = (wid >> 1) * 32;
    const int m0   = blockIdx.y * 128;
    const int n0   = blockIdx.x * 128;

    float acc[4][4][4];
#pragma unroll
    for (int i = 0; i < 4; i++)
#pragma unroll
        for (int j = 0; j < 4; j++)
#pragma unroll
            for (int t = 0; t < 4; t++) acc[i][j][t] = 0.f;

    for (int k0 = 0; k0 < Kdim; k0 += 32) {
#pragma unroll
        for (int i = 0; i < 4; i++) {
            int idx = tid + i * 256;
            int row = idx >> 3;
            int f4  = idx & 7;
            float4 a = *(const float4*)&A[(size_t)(m0 + row) * Kdim + k0 + f4 * 4];
            int w = row * 20 + f4 * 2;
            Ahi[w]     = bf16pair(a.x, a.y);
            Ahi[w + 1] = bf16pair(a.z, a.w);
            Alo[w]     = bf16pair(a.x - bf16hi(a.x), a.y - bf16hi(a.y));
            Alo[w + 1] = bf16pair(a.z - bf16hi(a.z), a.w - bf16hi(a.w));
        }
        {
            __nv_bfloat16* ph = reinterpret_cast<__nv_bfloat16*>(Bhi);
            __nv_bfloat16* pl = reinterpret_cast<__nv_bfloat16*>(Blo);
#pragma unroll
            for (int i = 0; i < 4; i++) {
                int idx = tid + i * 256;
                int kr  = idx >> 5;
                int n4  = (idx & 31) * 4;
                float4 b = *(const float4*)&Bm[(size_t)(k0 + kr) * Ndim + n0 + n4];
                int hb = ((kr >> 1) * 136) * 2 + (kr & 1);
                float vs[4] = {b.x, b.y, b.z, b.w};
#pragma unroll
                for (int j = 0; j < 4; j++) {
                    float v = vs[j];
                    __nv_bfloat16 h = __float2bfloat16(v);
                    ph[hb + (n4 + j) * 2] = h;
                    pl[hb + (n4 + j) * 2] = __float2bfloat16(v - __bfloat162float(h));
                }
            }
        }
        __syncthreads();

#pragma unroll
        for (int s = 0; s < 2; s++) {
            const int pb = s * 8 + tg;
            unsigned bh[4][2], bl[4][2];
#pragma unroll
            for (int nt = 0; nt < 4; nt++) {
                int c = wn + nt * 8 + g;
                bh[nt][0] = Bhi[pb * 136 + c];
                bh[nt][1] = Bhi[(pb + 4) * 136 + c];
                bl[nt][0] = Blo[pb * 136 + c];
                bl[nt][1] = Blo[(pb + 4) * 136 + c];
            }
#pragma unroll
            for (int mt = 0; mt < 4; mt++) {
                int r = wm + mt * 16 + g;
                unsigned ah[4], al[4];
                ah[0] = Ahi[r * 20 + pb];
                ah[1] = Ahi[(r + 8) * 20 + pb];
                ah[2] = Ahi[r * 20 + pb + 4];
                ah[3] = Ahi[(r + 8) * 20 + pb + 4];
                al[0] = Alo[r * 20 + pb];
                al[1] = Alo[(r + 8) * 20 + pb];
                al[2] = Alo[r * 20 + pb + 4];
                al[3] = Alo[(r + 8) * 20 + pb + 4];
#pragma unroll
                for (int nt = 0; nt < 4; nt++) {
                    mma16816(acc[mt][nt], ah, bh[nt]);
                    mma16816(acc[mt][nt], ah, bl[nt]);
                    mma16816(acc[mt][nt], al, bh[nt]);
                }
            }
        }
        __syncthreads();
    }

#pragma unroll
    for (int mt = 0; mt < 4; mt++) {
        int r = m0 + wm + mt * 16 + g;
#pragma unroll
        for (int nt = 0; nt < 4; nt++) {
            int c = n0 + wn + nt * 8 + tg * 2;
            float b0 = 0.f, b1 = 0.f;
            if (bias) { b0 = bias[c]; b1 = bias[c + 1]; }
            float2 v0 = make_float2(acc[mt][nt][0] + b0, acc[mt][nt][1] + b1);
            float2 v1 = make_float2(acc[mt][nt][2] + b0, acc[mt][nt][3] + b1);
            *(float2*)&Cm[(size_t)r * Ndim + c]       = v0;
            *(float2*)&Cm[(size_t)(r + 8) * Ndim + c] = v1;
        }
    }
}

// ---------------------------------------------------------------------------
// interaction_matrix transpose v3: (B, Tk, Tq, H) -> (B, H, Tq, Tk) with
// CAUSAL SKIP: attention (Br=128) never reads interT[q,k] with
// k/128 > q/128, so tiles with (k0>>7) > (q0>>7) are dead (~47% of grid).
// Dead region stays zero-/stale-finite: consumed only as (-inf + finite).
// ---------------------------------------------------------------------------
__global__ __launch_bounds__(256)
void transpose_inter3(const float* __restrict__ src, float* __restrict__ dst)
{
    if ((blockIdx.x >> 2) > (blockIdx.y >> 4)) return;   // k-blk128 > q-blk128

    __shared__ float s[32 * 129];
    const int t    = threadIdx.x;
    const int lane = t & 31;
    const int w    = t >> 5;
    const int k0   = blockIdx.x * 32;
    const int q0   = blockIdx.y * 8;
    const int b    = blockIdx.z;

    const int k  = t >> 3;
    const int f4b = t & 7;
    const float* sp = src + (size_t)(b * T_ + k0 + k) * (T_ * H_) + q0 * H_;
#pragma unroll
    for (int p = 0; p < 4; p++) {
        int f4 = f4b + p * 8;
        float4 v = *(const float4*)&sp[f4 * 4];
        s[k * 129 + f4 * 4 + 0] = v.x;
        s[k * 129 + f4 * 4 + 1] = v.y;
        s[k * 129 + f4 * 4 + 2] = v.z;
        s[k * 129 + f4 * 4 + 3] = v.w;
    }
    __syncthreads();

#pragma unroll
    for (int r = 0; r < 16; r++) {
        int qh = w * 16 + r;
        int q  = qh >> 4;
        int h  = qh & 15;
        float v = s[lane * 129 + qh];
        dst[((size_t)(b * H_ + h) * T_ + q0 + q) * T_ + k0 + lane] = v;
    }
}

// ---------------------------------------------------------------------------
// Tensor-core flash attention, bf16 2-term split, Br=128 / Bc=64.
// Grid (T/128, H, B), 256 threads = 8 warps, each warp owns 16 q-rows
// (w*16+g, +8) across the full 64-key tile -> intra-warp reductions only.
// Same per-warp inner loop as validated round 10; K/V tile load+convert and
// __syncthreads now amortized over 2x the mma work (tile-loads/bh: 136->72).
// K smem [key][dpair] stride 36, V smem [keypair][d] stride 72: conflict-free.
// ---------------------------------------------------------------------------
__global__ __launch_bounds__(256)
void attn_mma(const float* __restrict__ Q, const float* __restrict__ K,
              const float* __restrict__ V, const int* __restrict__ pad,
              const float* __restrict__ interT, float* __restrict__ ctx)
{
    __shared__ unsigned Khi[64 * 36], Klo[64 * 36];
    __shared__ unsigned Vhi[32 * 72], Vlo[32 * 72];

    const float NEG = __int_as_float(0xff800000);   // -inf

    const int tid  = threadIdx.x;
    const int lane = tid & 31;
    const int w    = tid >> 5;        // warp 0..7
    const int g    = lane >> 2;       // 0..7
    const int tg   = lane & 3;        // 0..3
    const int q0   = blockIdx.x * 128;
    const int h    = blockIdx.y;
    const int b    = blockIdx.z;

    const int row0 = q0 + w * 16 + g;     // q row for accum c0,c1
    const int row1 = row0 + 8;            // q row for accum c2,c3

    // ---- Q fragments in registers (scaled by 0.125 = exact) ----
    unsigned ah[4][4], al[4][4];
#pragma unroll
    for (int rsel = 0; rsel < 2; rsel++) {
        int row = rsel ? row1 : row0;
        const float* qp = Q + (size_t)(b * T_ + row) * C_ + h * D_ + 2 * tg;
#pragma unroll
        for (int m = 0; m < 8; m++) {
            float2 v = *(const float2*)&qp[m * 8];
            v.x *= 0.125f; v.y *= 0.125f;
            int s   = m >> 1;
            int idx = ((m & 1) << 1) | rsel;
            split2(ah[s][idx], al[s][idx], v.x, v.y);
        }
    }

    const int pd0 = pad[b * T_ + row0];
    const int pd1 = pad[b * T_ + row1];
    const float* ip0 = interT + ((size_t)(b * H_ + h) * T_ + row0) * T_ + 2 * tg;
    const float* ip1 = interT + ((size_t)(b * H_ + h) * T_ + row1) * T_ + 2 * tg;

    float m0 = NEG, m1 = NEG, l0 = 0.f, l1 = 0.f;
    float o[8][4];
#pragma unroll
    for (int j = 0; j < 8; j++)
#pragma unroll
        for (int i = 0; i < 4; i++) o[j][i] = 0.f;

    const float* kbase = K + (size_t)(b * T_) * C_ + h * D_;
    const float* vbase = V + (size_t)(b * T_) * C_ + h * D_;

    for (int k0 = 0; k0 < q0 + 128; k0 += 64) {
        __syncthreads();   // smem consumed by previous iteration's mma
        // ---- K tile: 64 keys x 64 d -> hi/lo pairs [key][dpair] ----
#pragma unroll
        for (int i = 0; i < 4; i++) {
            int idx = tid + i * 256;
            int kr  = idx >> 4;
            int d4  = (idx & 15) * 4;
            float4 kv = *(const float4*)&kbase[(size_t)(k0 + kr) * C_ + d4];
            int wb = kr * 36 + d4 / 2;
            unsigned h0, l0w, h1, l1w;
            split2(h0, l0w, kv.x, kv.y);
            split2(h1, l1w, kv.z, kv.w);
            Khi[wb] = h0; Khi[wb + 1] = h1;
            Klo[wb] = l0w; Klo[wb + 1] = l1w;
        }
        // ---- V tile: 64 keys x 64 d -> key-pair packed [kp][d] ----
        {
            __nv_bfloat16* vh = reinterpret_cast<__nv_bfloat16*>(Vhi);
            __nv_bfloat16* vl = reinterpret_cast<__nv_bfloat16*>(Vlo);
#pragma unroll
            for (int i = 0; i < 4; i++) {
                int idx = tid + i * 256;
                int vr  = idx >> 4;
                int d4  = (idx & 15) * 4;
                float4 vv = *(const float4*)&vbase[(size_t)(k0 + vr) * C_ + d4];
                int half = vr & 1;
                int wb   = (vr >> 1) * 72 + d4;
                float vs[4] = {vv.x, vv.y, vv.z, vv.w};
#pragma unroll
                for (int j = 0; j < 4; j++) {
                    __nv_bfloat16 hv = __float2bfloat16(vs[j]);
                    vh[(wb + j) * 2 + half] = hv;
                    vl[(wb + j) * 2 + half] =
                        __float2bfloat16(vs[j] - __bfloat162float(hv));
                }
            }
        }
        __syncthreads();

        // ---- bias loads (independent of mma; compiler overlaps) ----
        float2 bias0[8], bias1[8];
#pragma unroll
        for (int j = 0; j < 8; j++) {
            bias0[j] = *(const float2*)&ip0[k0 + 8 * j];
            bias1[j] = *(const float2*)&ip1[k0 + 8 * j];
        }

        // ---- S = (0.125*Q) K^T via split mma ----
        float sc[8][4];
#pragma unroll
        for (int j = 0; j < 8; j++)
#pragma unroll
            for (int i = 0; i < 4; i++) sc[j][i] = 0.f;
#pragma unroll
        for (int j = 0; j < 8; j++) {
            const int c = (8 * j + g) * 36;
#pragma unroll
            for (int st = 0; st < 4; st++) {
                unsigned bh[2] = {Khi[c + st * 8 + tg], Khi[c + st * 8 + tg + 4]};
                unsigned bl[2] = {Klo[c + st * 8 + tg], Klo[c + st * 8 + tg + 4]};
                mma16816(sc[j], ah[st], bh);
                mma16816(sc[j], ah[st], bl);
                mma16816(sc[j], al[st], bh);
            }
        }

        // ---- masks + bias + online softmax ----
        float mt0 = NEG, mt1 = NEG;
#pragma unroll
        for (int j = 0; j < 8; j++) {
            int kc = k0 + 8 * j + 2 * tg;
            float v0 = sc[j][0], v1 = sc[j][1], v2 = sc[j][2], v3 = sc[j][3];
            if (pd0 == 0) { v0 = -1e9f; v1 = -1e9f; }
            if (pd1 == 0) { v2 = -1e9f; v3 = -1e9f; }
            if (kc     > row0) v0 = NEG;
            if (kc + 1 > row0) v1 = NEG;
            if (kc     > row1) v2 = NEG;
            if (kc + 1 > row1) v3 = NEG;
            v0 += bias0[j].x; v1 += bias0[j].y;
            v2 += bias1[j].x; v3 += bias1[j].y;
            sc[j][0] = v0; sc[j][1] = v1; sc[j][2] = v2; sc[j][3] = v3;
            mt0 = fmaxf(mt0, fmaxf(v0, v1));
            mt1 = fmaxf(mt1, fmaxf(v2, v3));
        }
        mt0 = fmaxf(mt0, __shfl_xor_sync(0xffffffffu, mt0, 1));
        mt0 = fmaxf(mt0, __shfl_xor_sync(0xffffffffu, mt0, 2));
        mt1 = fmaxf(mt1, __shfl_xor_sync(0xffffffffu, mt1, 1));
        mt1 = fmaxf(mt1, __shfl_xor_sync(0xffffffffu, mt1, 2));

        float mn0 = fmaxf(m0, mt0), mn1 = fmaxf(m1, mt1);
        float f0 = __expf(m0 - mn0);   // m0=-inf first tile -> 0
        float f1 = __expf(m1 - mn1);

        float lt0 = 0.f, lt1 = 0.f;
#pragma unroll
        for (int j = 0; j < 8; j++) {
            float p0 = __expf(sc[j][0] - mn0);   // -inf -> 0 (mn finite)
            float p1 = __expf(sc[j][1] - mn0);
            float p2 = __expf(sc[j][2] - mn1);
            float p3 = __expf(sc[j][3] - mn1);
            sc[j][0] = p0; sc[j][1] = p1; sc[j][2] = p2; sc[j][3] = p3;
            lt0 += p0 + p1; lt1 += p2 + p3;
        }
        lt0 += __shfl_xor_sync(0xffffffffu, lt0, 1);
        lt0 += __shfl_xor_sync(0xffffffffu, lt0, 2);
        lt1 += __shfl_xor_sync(0xffffffffu, lt1, 1);
        lt1 += __shfl_xor_sync(0xffffffffu, lt1, 2);
        l0 = l0 * f0 + lt0; m0 = mn0;
        l1 = l1 * f1 + lt1; m1 = mn1;

#pragma unroll
        for (int j = 0; j < 8; j++) {
            o[j][0] *= f0; o[j][1] *= f0;
            o[j][2] *= f1; o[j][3] *= f1;
        }

        // ---- P fragments: S accum layout == A-frag layout ----
        unsigned ph[4][4], pl[4][4];
#pragma unroll
        for (int s = 0; s < 4; s++) {
            split2(ph[s][0], pl[s][0], sc[2 * s][0],     sc[2 * s][1]);
            split2(ph[s][1], pl[s][1], sc[2 * s][2],     sc[2 * s][3]);
            split2(ph[s][2], pl[s][2], sc[2 * s + 1][0], sc[2 * s + 1][1]);
            split2(ph[s][3], pl[s][3], sc[2 * s + 1][2], sc[2 * s + 1][3]);
        }

        // ---- O += P V via split mma ----
#pragma unroll
        for (int j = 0; j < 8; j++) {
            const int c = 8 * j + g;
#pragma unroll
            for (int s = 0; s < 4; s++) {
                unsigned bh[2] = {Vhi[(s * 8 + tg) * 72 + c],
                                  Vhi[(s * 8 + tg + 4) * 72 + c]};
                unsigned bl[2] = {Vlo[(s * 8 + tg) * 72 + c],
                                  Vlo[(s * 8 + tg + 4) * 72 + c]};
                mma16816(o[j], ph[s], bh);
                mma16816(o[j], ph[s], bl);
                mma16816(o[j], pl[s], bh);
            }
        }
    }

    // ---- epilogue: normalize, write ctx (B,T,C) ----
    const float inv0 = 1.f / l0, inv1 = 1.f / l1;
    float* op0 = ctx + (size_t)(b * T_ + row0) * C_ + h * D_ + 2 * tg;
    float* op1 = ctx + (size_t)(b * T_ + row1) * C_ + h * D_ + 2 * tg;
#pragma unroll
    for (int j = 0; j < 8; j++) {
        *(float2*)&op0[8 * j] = make_float2(o[j][0] * inv0, o[j][1] * inv0);
        *(float2*)&op1[8 * j] = make_float2(o[j][2] * inv1, o[j][3] * inv1);
    }
}

// ---------------------------------------------------------------------------
// Launch: 5 projection GEMMs (tensor-core), causal-skip transpose, Br=128
// mma attention, output GEMM. Default stream, graph-capturable.
// ---------------------------------------------------------------------------
extern "C" void kernel_launch(void* const* d_in, const int* in_sizes, int n_in,
                              void* d_out, int out_size)
{
    const float* x       = (const float*)d_in[0];
    const int*   padding = (const int*)  d_in[1];
    const float* inter   = (const float*)d_in[2];
    const float* W_ckv   = (const float*)d_in[3];
    const float* W_cq    = (const float*)d_in[4];
    const float* W_kc    = (const float*)d_in[5];
    const float* W_qc    = (const float*)d_in[6];
    const float* W_vc    = (const float*)d_in[7];
    const float* W_proj  = (const float*)d_in[8];
    const float* b_proj  = (const float*)d_in[9];
    float* out = (float*)d_out;

    float *kv_down, *q_down, *kb, *qb, *vb, *ctx, *interT;
    cudaGetSymbolAddress((void**)&kv_down, g_kv_down);
    cudaGetSymbolAddress((void**)&q_down,  g_q_down);
    cudaGetSymbolAddress((void**)&kb,      g_k);
    cudaGetSymbolAddress((void**)&qb,      g_q);
    cudaGetSymbolAddress((void**)&vb,      g_v);
    cudaGetSymbolAddress((void**)&ctx,     g_ctx);
    cudaGetSymbolAddress((void**)&interT,  g_interT);

    dim3 blk(256);

    // down projections: (4096x1024)@(1024x256)
    hgemm_bf16x3<<<dim3(L_ / 128, M_ / 128), blk>>>(x, W_ckv, kv_down, M_, L_, C_, nullptr);
    hgemm_bf16x3<<<dim3(L_ / 128, M_ / 128), blk>>>(x, W_cq,  q_down,  M_, L_, C_, nullptr);

    // up projections: (4096x256)@(256x1024), (B,T,C) layout == (B,T,H,D)
    hgemm_bf16x3<<<dim3(C_ / 128, M_ / 128), blk>>>(kv_down, W_kc, kb, M_, C_, L_, nullptr);
    hgemm_bf16x3<<<dim3(C_ / 128, M_ / 128), blk>>>(q_down,  W_qc, qb, M_, C_, L_, nullptr);
    hgemm_bf16x3<<<dim3(C_ / 128, M_ / 128), blk>>>(kv_down, W_vc, vb, M_, C_, L_, nullptr);

    // interaction matrix (B,Tk,Tq,H) -> (B,H,Tq,Tk), causal tiles only
    transpose_inter3<<<dim3(T_ / 32, T_ / 8, B_), blk>>>(inter, interT);

    // attention -> ctx (B,T,C), Br=128
    attn_mma<<<dim3(T_ / 128, H_, B_), dim3(256)>>>(qb, kb, vb, padding, interT, ctx);

    // output projection: (4096x1024)@(1024x1024) + bias
    hgemm_bf16x3<<<dim3(C_ / 128, M_ / 128), blk>>>(ctx, W_proj, out, M_, C_, C_, b_proj);
}